// round 14
// baseline (speedup 1.0000x reference)
#include <cuda_runtime.h>
#include <cuda_fp16.h>
#include <cuda_fp8.h>
#include <stdint.h>

// Problem constants
#define NS   36      // streams
#define HH   256     // hidden
#define GWW  1024    // gate width
#define BB   32      // batch
#define TST  128     // timesteps
#define FEAT 9472    // (NS+1)*HH

#define SLOT_BYTES 1536    // one stage: 1024 B hi (fp16) + 512 B lo (fp8)
// SMEM: [A stage-in area: 64 KB][ring]
//  L1 blocks: A uses 32 KB, ring 8w x 4 slots @32 KB offset (48 KB) -> 80 KB used
//  L2 blocks: A uses 64 KB, ring 8w x 3 slots @64 KB offset (36 KB) -> 100 KB used
#define SMEM_BYTES (65536 + 8 * 3 * SLOT_BYTES)   // 102400
#define NB 288             // persistent grid size (<= 2 blocks/SM * SMs)

// ---------------- device scratch (static; no allocation) ----------------
// Weight hi plane: fp16 fragments. Per (m,n): 2048 frags; frag = w8g*64 + ks*4 + ctl.
// hi frag = 32 lanes * 4 halves = 256 B. Stage block (4 frags) = 1024 B contiguous.
__device__ __align__(1024) __half  g_Bhi[3u * NS * 2048u * 128u];   // 56.6 MB
// Weight lo plane: e5m2 bytes of (Wlo * 2^12). Stage block = 512 B contiguous.
__device__ __align__(1024) uint8_t g_Blo[3u * NS * 2048u * 128u];   // 28.3 MB
// h buffers, planar hi/lo: plane0 (hi) [ks][rt][lane][8 halves] = 8192 halves,
// plane1 (lo) at +8192 halves (16 KB).
__device__ __align__(1024) __half g_H1[2][NS][16384];
__device__ __align__(1024) __half g_H2[2][NS][16384];
__device__ float  g_c1[NS * HH * BB];
__device__ float  g_c2[NS * HH * BB];
__device__ float  g_Wih1p[NS * GWW];                   // permuted gate order (u*4+gt)
__device__ float  g_bg1p[NS * GWW];
__device__ float  g_bg2p[NS * GWW];
__device__ float  g_featT[FEAT * BB];                  // featT[k][b]
__device__ float  g_act[BB * HH];                      // fc1 output (post-ReLU)

// grid barrier: per-block monotone flags (padded) + release word (replay-safe).
__device__ volatile unsigned g_flags[NB * 32];
__device__ volatile unsigned g_rel;

// ---------------- PTX helpers ----------------
__device__ __forceinline__ uint32_t smem_u32(const void* p) {
    uint32_t a;
    asm("{ .reg .u64 t; cvta.to.shared.u64 t, %1; cvt.u32.u64 %0, t; }" : "=r"(a) : "l"(p));
    return a;
}
__device__ __forceinline__ void cp_async16(uint32_t dst, const void* src) {
    asm volatile("cp.async.cg.shared.global [%0], [%1], 16;" :: "r"(dst), "l"(src) : "memory");
}
__device__ __forceinline__ void cp_commit() {
    asm volatile("cp.async.commit_group;" ::: "memory");
}
__device__ __forceinline__ void lds128v(uint4& v, uint32_t addr) {
    asm volatile("ld.shared.v4.b32 {%0,%1,%2,%3}, [%4];"
                 : "=r"(v.x), "=r"(v.y), "=r"(v.z), "=r"(v.w) : "r"(addr));
}
__device__ __forceinline__ void lds64v(uint2& v, uint32_t addr) {
    asm volatile("ld.shared.v2.b32 {%0,%1}, [%2];" : "=r"(v.x), "=r"(v.y) : "r"(addr));
}
__device__ __forceinline__ uint32_t lds32(uint32_t addr) {
    uint32_t v;
    asm volatile("ld.shared.b32 %0, [%1];" : "=r"(v) : "r"(addr));
    return v;
}
__device__ __forceinline__ uint32_t mulf16x2(uint32_t a, uint32_t b) {
    uint32_t d;
    asm("mul.f16x2 %0, %1, %2;" : "=r"(d) : "r"(a), "r"(b));
    return d;
}
__device__ __forceinline__ void mma16816(float c[4],
                                         uint32_t a0, uint32_t a1, uint32_t a2, uint32_t a3,
                                         uint32_t b0, uint32_t b1) {
    asm volatile(
        "mma.sync.aligned.m16n8k16.row.col.f32.f16.f16.f32 "
        "{%0,%1,%2,%3}, {%4,%5,%6,%7}, {%8,%9}, {%0,%1,%2,%3};"
        : "+f"(c[0]), "+f"(c[1]), "+f"(c[2]), "+f"(c[3])
        : "r"(a0), "r"(a1), "r"(a2), "r"(a3), "r"(b0), "r"(b1));
}
__device__ __forceinline__ float sigf(float v) { return 1.0f / (1.0f + expf(-v)); }

// Flag-array grid barrier (all NB blocks co-resident, single wave).
__device__ __forceinline__ void grid_barrier(unsigned target) {
    __syncthreads();
    if (blockIdx.x == 0) {
        if (threadIdx.x == 0) {
            __threadfence();
            g_flags[0] = target;
        }
        for (int j = threadIdx.x; j < NB; j += 256) {
            while (g_flags[j * 32] < target) { }
        }
        __syncthreads();
        if (threadIdx.x == 0) {
            __threadfence();
            g_rel = target;
        }
    } else {
        if (threadIdx.x == 0) {
            __threadfence();
            g_flags[blockIdx.x * 32] = target;
            while (g_rel < target) { }
        }
    }
    __syncthreads();
    __threadfence();
}

// ---------------- setup kernels ----------------
// Convert big weights fp32 -> hi plane (fp16) + lo plane (e5m2 of Wlo*2^12).
__global__ void conv_big(const float* __restrict__ Whh1,
                         const float* __restrict__ Wih2,
                         const float* __restrict__ Whh2) {
    int idx = blockIdx.x * 256 + threadIdx.x;        // 3*36*2048*32 = 7,077,888
    if (idx >= 3 * NS * 2048 * 32) return;
    int lane = idx & 31;
    int r    = idx >> 5;
    int frag = r & 2047;          // w8g*64 + ks*4 + ctl
    int r2   = r >> 11;
    int n    = r2 % NS;
    int m    = r2 / NS;
    int ctl  = frag & 3;
    int ks   = (frag >> 2) & 15;
    int w8g  = frag >> 6;         // [0,32): global warp-column index
    int col  = w8g * 32 + ctl * 8 + (lane >> 2);   // permuted gate-col [0,1024)
    int i4   = lane & 3;
    int u    = col >> 2;
    int gt   = col & 3;
    int g_orig = gt * 256 + u;    // original torch gate index
    const float* W = (m == 0) ? Whh1 : ((m == 1) ? Wih2 : Whh2);
    const float* src = W + ((size_t)n * GWW + g_orig) * HH + ks * 16;
    size_t fragGlobal = (size_t)(m * NS + n) * 2048 + frag;
    __half*  hiDst = g_Bhi + fragGlobal * 128 + lane * 4;
    uint8_t* loDst = g_Blo + fragGlobal * 128 + lane * 4;
    int kk0 = 2 * i4;
    int kks[4] = {kk0, kk0 + 1, kk0 + 8, kk0 + 9};
#pragma unroll
    for (int j = 0; j < 4; j++) {
        float v = src[kks[j]];
        __half hi = __float2half_rn(v);
        float rlo = (v - __half2float(hi)) * 4096.0f;   // 2^12 pre-scale
        __nv_fp8_e5m2 f8(rlo);                          // RN to e5m2
        hiDst[j] = hi;
        loDst[j] = *reinterpret_cast<uint8_t*>(&f8);
    }
}

// Permute Wih1 and fused biases into u*4+gt order.
__global__ void conv_small(const float* __restrict__ Wih1,
                           const float* __restrict__ bih1, const float* __restrict__ bhh1,
                           const float* __restrict__ bih2, const float* __restrict__ bhh2) {
    int idx = blockIdx.x * 256 + threadIdx.x;        // 36*1024
    if (idx >= NS * GWW) return;
    int n = idx >> 10;
    int col = idx & 1023;
    int u = col >> 2, gt = col & 3;
    int go = gt * 256 + u;
    int s = n * GWW + go;
    g_Wih1p[idx] = Wih1[s];
    g_bg1p[idx]  = bih1[s] + bhh1[s];
    g_bg2p[idx]  = bih2[s] + bhh2[s];
}

__global__ void init_kernel() {
    int idx = blockIdx.x * 256 + threadIdx.x;
    if (idx < 2 * NS * 16384 / 2) {                  // both parities
        ((uint32_t*)g_H1)[idx] = 0u;
        ((uint32_t*)g_H2)[idx] = 0u;
    }
    if (idx < NS * HH * BB) {
        g_c1[idx] = 0.f;
        g_c2[idx] = 0.f;
    }
}

// ---------------- GEMM stage machine (templated on ring shape) ----------------
// A (h planes) staged into SMEM as cp.async group 0 (block-cooperative).
// Ring: per-warp DEPTHT slots, pipeline distance DIST, in-loop wait keeps WAITN
// groups pending. Stage-0 wait is followed by __syncthreads (A copied by ALL
// threads); later stages only need __syncwarp (ring bytes copied by own warp).
template <int DEPTHT, int DIST, int WAITN, int S>
__device__ __forceinline__ void gemm_stages(
    float acc[2][4][4], uint32_t aSmem, uint32_t ringBase,
    const char* __restrict__ a0g, const char* __restrict__ a1g,
    const char* __restrict__ BhiBase, const char* __restrict__ BloBase,
    size_t warpHi0, size_t warpHi1, size_t warpLo0, size_t warpLo1,
    int lane, int tid)
{
    uint32_t laneOff = (uint32_t)lane * 16;

    // A stage-in: 32 KB per source, one commit group total
    for (int i = tid * 16; i < 32768; i += 4096)
        cp_async16(aSmem + i, a0g + i);
    if (S == 32)
        for (int i = tid * 16; i < 32768; i += 4096)
            cp_async16(aSmem + 32768 + i, a1g + i);
    cp_commit();

    // ring prologue: stages 0..DIST-1
#pragma unroll
    for (int s = 0; s < DIST; s++) {
        size_t hoff = ((s < 16) ? warpHi0 : warpHi1) + (size_t)(s & 15) * 1024;
        size_t loff = ((s < 16) ? warpLo0 : warpLo1) + (size_t)(s & 15) * 512;
        uint32_t dst = ringBase + (uint32_t)(s % DEPTHT) * SLOT_BYTES;
        cp_async16(dst + laneOff,        BhiBase + hoff + laneOff);
        cp_async16(dst + 512 + laneOff,  BhiBase + hoff + 512 + laneOff);
        cp_async16(dst + 1024 + laneOff, BloBase + loff + laneOff);
        cp_commit();
    }

    for (int s = 0; s < S; s++) {
        int slot = s % DEPTHT;
        asm volatile("cp.async.wait_group %0;" :: "n"(WAITN) : "memory");
        if (s == 0) __syncthreads();   // block-wide A copy visible to all warps
        else        __syncwarp();      // ring slot copied by own warp's lanes
        int ks = s & 15;

        uint32_t aAddr = aSmem + ((s < 16) ? 0u : 32768u) + (uint32_t)(ks * 2) * 512 + laneOff;
        uint4 ahi[2], alo[2];
#pragma unroll
        for (int rt = 0; rt < 2; rt++) {
            lds128v(ahi[rt], aAddr + rt * 512);
            lds128v(alo[rt], aAddr + rt * 512 + 16384);   // lo plane at +16 KB
        }
        uint32_t slotAddr = ringBase + slot * SLOT_BYTES;
        uint2 bhi[4];
        uint32_t lo32[4];
#pragma unroll
        for (int ctl = 0; ctl < 4; ctl++) {
            lds64v(bhi[ctl], slotAddr + ctl * 256 + lane * 8);
            lo32[ctl] = lds32(slotAddr + 1024 + ctl * 128 + lane * 4);
        }

        // refill slot for stage s+DIST
        int s2 = s + DIST;
        if (s2 < S) {
            size_t hoff = ((s2 < 16) ? warpHi0 : warpHi1) + (size_t)(s2 & 15) * 1024;
            size_t loff = ((s2 < 16) ? warpLo0 : warpLo1) + (size_t)(s2 & 15) * 512;
            uint32_t dst = ringBase + (uint32_t)(s2 % DEPTHT) * SLOT_BYTES;
            cp_async16(dst + laneOff,        BhiBase + hoff + laneOff);
            cp_async16(dst + 512 + laneOff,  BhiBase + hoff + 512 + laneOff);
            cp_async16(dst + 1024 + laneOff, BloBase + loff + laneOff);
        }
        cp_commit();

#pragma unroll
        for (int ctl = 0; ctl < 4; ctl++) {
            // expand e5m2 -> fp16 (exact: byte<<8), rescale by 2^-12 (exact)
            uint32_t l0 = __byte_perm(lo32[ctl], 0u, 0x1404);
            uint32_t l1 = __byte_perm(lo32[ctl], 0u, 0x3424);
            l0 = mulf16x2(l0, 0x0C000C00u);
            l1 = mulf16x2(l1, 0x0C000C00u);
#pragma unroll
            for (int rt = 0; rt < 2; rt++) {
                mma16816(acc[rt][ctl], ahi[rt].x, ahi[rt].y, ahi[rt].z, ahi[rt].w, bhi[ctl].x, bhi[ctl].y);  // Hhi*Whi
                mma16816(acc[rt][ctl], ahi[rt].x, ahi[rt].y, ahi[rt].z, ahi[rt].w, l0, l1);                  // Hhi*Wlo
                mma16816(acc[rt][ctl], alo[rt].x, alo[rt].y, alo[rt].z, alo[rt].w, bhi[ctl].x, bhi[ctl].y);  // Hlo*Whi
            }
        }
    }
    asm volatile("cp.async.wait_group 0;" ::: "memory");
}

// ---------------- persistent step kernel ----------------
// blocks [0,144) = layer1, [144,288) = layer2 (one step behind); 129 iterations
// separated by the flag-array grid barrier. 8 warps/block; warp w8 owns 32
// output cols (4 ct-tiles).
__global__ void __launch_bounds__(256, 2) steps_kernel(
    const float* __restrict__ x,
    const float* __restrict__ spec,
    const float* __restrict__ Wspec,
    const float* __restrict__ bspec) {
    extern __shared__ __align__(128) unsigned char smem[];
    uint32_t smem_base = smem_u32(smem);

    int bid = blockIdx.x;
    bool isL2 = (bid >= 144);
    int lb = isL2 ? bid - 144 : bid;
    int n = lb >> 2, bl = lb & 3;
    int tid = threadIdx.x, w8 = tid >> 5, lane = tid & 31;
    int w8g = bl * 8 + w8;

    unsigned bar_base = g_flags[bid * 32];   // monotone across replays

    const int m0 = isL2 ? 1 : 0;
    const char* BhiBase = (const char*)g_Bhi;
    const char* BloBase = (const char*)g_Blo;
    const size_t warpHi0 = ((size_t)((m0 * NS) + n) * 2048 + (size_t)w8g * 64) * 256;
    const size_t warpHi1 = ((size_t)(((m0 + 1) * NS) + n) * 2048 + (size_t)w8g * 64) * 256;
    const size_t warpLo0 = ((size_t)((m0 * NS) + n) * 2048 + (size_t)w8g * 64) * 128;
    const size_t warpLo1 = ((size_t)(((m0 + 1) * NS) + n) * 2048 + (size_t)w8g * 64) * 128;

    // ring base per block type (A area in front: 32 KB for L1, 64 KB for L2)
    uint32_t ringBase = isL2 ? (smem_base + 65536u + (uint32_t)w8 * (3 * SLOT_BYTES))
                             : (smem_base + 32768u + (uint32_t)w8 * (4 * SLOT_BYTES));

    float* cbuf = isL2 ? g_c2 : g_c1;
    const float* bias = isL2 ? g_bg2p : g_bg1p;

    for (int t = 0; t <= TST; t++) {
        int st = isL2 ? t - 1 : t;
        if (st >= 0 && st < TST) {
            int rp = st & 1, wp = rp ^ 1;

            float acc[2][4][4];
#pragma unroll
            for (int a = 0; a < 2; a++)
#pragma unroll
                for (int b = 0; b < 4; b++)
#pragma unroll
                    for (int c = 0; c < 4; c++) acc[a][b][c] = 0.f;

            if (!isL2) {
                const char* a0g = (const char*)g_H1[rp][n];
                gemm_stages<4, 3, 2, 16>(acc, smem_base, ringBase, a0g, a0g,
                                         BhiBase, BloBase,
                                         warpHi0, warpHi0, warpLo0, warpLo0, lane, tid);
            } else {
                const char* a0g = (const char*)g_H1[wp][n];   // h1(st)
                const char* a1g = (const char*)g_H2[rp][n];   // h2(st-1)
                gemm_stages<3, 2, 1, 32>(acc, smem_base, ringBase, a0g, a1g,
                                         BhiBase, BloBase,
                                         warpHi0, warpHi1, warpLo0, warpLo1, lane, tid);
            }

            // sg overlays the A area (dead after mainloop)
            __syncthreads();
            float* sg = (float*)smem;            // 32 KB

            int g8 = lane >> 2;
            int i2 = (lane & 3) * 2;
#pragma unroll
            for (int rt = 0; rt < 2; rt++)
#pragma unroll
                for (int ctl = 0; ctl < 4; ctl++) {
                    int col = w8 * 32 + ctl * 8 + i2;
                    int r0 = rt * 16 + g8;
                    sg[r0 * 256 + col]           = acc[rt][ctl][0];
                    sg[r0 * 256 + col + 1]       = acc[rt][ctl][1];
                    sg[(r0 + 8) * 256 + col]     = acc[rt][ctl][2];
                    sg[(r0 + 8) * 256 + col + 1] = acc[rt][ctl][3];
                }
            __syncthreads();

            __half* Hout = isL2 ? g_H2[wp][n] : g_H1[wp][n];

            for (int e = tid; e < BB * 64; e += 256) {
                int b  = e & 31;
                int ul = e >> 5;                 // local unit [0,64)
                int u  = bl * 64 + ul;           // unit [0,256)
                int cb = ul * 4;
                int colg = bl * 256 + cb;        // permuted col within stream
                float ip = sg[b * 256 + cb + 0] + bias[n * GWW + colg + 0];
                float fp = sg[b * 256 + cb + 1] + bias[n * GWW + colg + 1];
                float gp = sg[b * 256 + cb + 2] + bias[n * GWW + colg + 2];
                float op = sg[b * 256 + cb + 3] + bias[n * GWW + colg + 3];
                if (!isL2) {
                    float xv = x[(b * TST + st) * NS + n];
                    ip += xv * g_Wih1p[n * GWW + colg + 0];
                    fp += xv * g_Wih1p[n * GWW + colg + 1];
                    gp += xv * g_Wih1p[n * GWW + colg + 2];
                    op += xv * g_Wih1p[n * GWW + colg + 3];
                }
                float iv = sigf(ip), fv = sigf(fp), gv = tanhf(gp), ov = sigf(op);
                int ci = (n * HH + u) * BB + b;
                float cv = fv * cbuf[ci] + iv * gv;
                cbuf[ci] = cv;
                float hv = ov * tanhf(cv);

                // write h into planar A-fragment layout (hi plane, lo plane)
                int ks = u >> 4, kk = u & 15;
                int rt = b >> 4, rl = b & 15;
                int gg = rl & 7, hirow = rl >> 3;
                int ii = (kk & 7) >> 1, p = kk & 1, hik = kk >> 3;
                int lane2 = gg * 4 + ii;
                int j = hik * 4 + hirow * 2 + p;
                __half hi = __float2half_rn(hv);
                __half lo = __float2half_rn(hv - __half2float(hi));
                __half* hp = Hout + ((ks * 2 + rt) * 32 + lane2) * 8 + j;
                hp[0]    = hi;
                hp[8192] = lo;                   // lo plane at +16 KB

                if (isL2) g_featT[(n * HH + u) * BB + b] = hv;
            }
        } else if (!isL2 && bid == 0 && t == TST) {
            // idle final iteration: compute spec-dense rows of featT
            int j = tid;                         // [0,256)
            for (int b = 0; b < BB; b++) {
                float s = bspec[j];
#pragma unroll
                for (int i = 0; i < 6; i++) s += spec[b * 6 + i] * Wspec[i * HH + j];
                g_featT[(NS * HH + j) * BB + b] = s;
            }
        }

        grid_barrier(bar_base + (unsigned)t + 1u);   // publishes h(t)
    }
}

// ---------------- classifier ----------------
__global__ void fc1_kernel(const float* __restrict__ Wp1, const float* __restrict__ bp1) {
    int tid = threadIdx.x;
    int b = tid & 31;
    int tj = tid >> 5;                      // [0,8)
    int j = blockIdx.x * 8 + tj;            // [0,256)
    const float* ft = g_featT + b;
    const float* wc = Wp1 + j;
    float a0 = 0.f, a1 = 0.f, a2 = 0.f, a3 = 0.f;
#pragma unroll 4
    for (int k = 0; k < FEAT; k += 4) {
        a0 += ft[(k + 0) * BB] * wc[(size_t)(k + 0) * HH];
        a1 += ft[(k + 1) * BB] * wc[(size_t)(k + 1) * HH];
        a2 += ft[(k + 2) * BB] * wc[(size_t)(k + 2) * HH];
        a3 += ft[(k + 3) * BB] * wc[(size_t)(k + 3) * HH];
    }
    float acc = bp1[j] + ((a0 + a1) + (a2 + a3));
    g_act[b * HH + j] = fmaxf(acc, 0.f);
}

__global__ void fc2_kernel(const float* __restrict__ Wp2, const float* __restrict__ bp2,
                           float* __restrict__ out) {
    int tid = threadIdx.x;
    if (tid >= BB * 30) return;
    int b = tid / 30, o = tid % 30;
    float acc = bp2[o];
#pragma unroll 8
    for (int k = 0; k < HH; k++) acc += g_act[b * HH + k] * Wp2[k * 30 + o];
    out[b * 30 + o] = acc;
}

// ---------------- launch ----------------
extern "C" void kernel_launch(void* const* d_in, const int* in_sizes, int n_in,
                              void* d_out, int out_size) {
    const float* x     = (const float*)d_in[0];
    const float* spec  = (const float*)d_in[1];
    const float* Wih1  = (const float*)d_in[2];
    const float* Whh1  = (const float*)d_in[3];
    const float* bih1  = (const float*)d_in[4];
    const float* bhh1  = (const float*)d_in[5];
    const float* Wih2  = (const float*)d_in[6];
    const float* Whh2  = (const float*)d_in[7];
    const float* bih2  = (const float*)d_in[8];
    const float* bhh2  = (const float*)d_in[9];
    const float* Wspec = (const float*)d_in[10];
    const float* bspec = (const float*)d_in[11];
    const float* Wp1   = (const float*)d_in[12];
    const float* bp1   = (const float*)d_in[13];
    const float* Wp2   = (const float*)d_in[14];
    const float* bp2   = (const float*)d_in[15];
    float* out = (float*)d_out;

    cudaFuncSetAttribute(steps_kernel, cudaFuncAttributeMaxDynamicSharedMemorySize, SMEM_BYTES);

    conv_big<<<27648, 256>>>(Whh1, Wih2, Whh2);
    conv_small<<<144, 256>>>(Wih1, bih1, bhh1, bih2, bhh2);
    init_kernel<<<2304, 256>>>();

    steps_kernel<<<NB, 256, SMEM_BYTES>>>(x, spec, Wspec, bspec);

    fc1_kernel<<<32, 256>>>(Wp1, bp1);
    fc2_kernel<<<1, 960>>>(Wp2, bp2, out);
}

// round 15
// speedup vs baseline: 1.2427x; 1.2427x over previous
#include <cuda_runtime.h>
#include <cuda_fp16.h>
#include <cuda_fp8.h>
#include <stdint.h>

// Problem constants
#define NS   36      // streams
#define HH   256     // hidden
#define GWW  1024    // gate width
#define BB   32      // batch
#define TST  128     // timesteps
#define FEAT 9472    // (NS+1)*HH

#define DEPTH 4            // ring slots per warp
#define SLOT_BYTES 1536    // one stage: 1024 B hi (fp16) + 512 B lo (fp8)
#define RING_BYTES (8 * DEPTH * SLOT_BYTES)      // 49152
#define SMEM_BYTES RING_BYTES
#define NB 288             // persistent grid size (<= 2 blocks/SM * SMs)

// ---------------- device scratch (static; no allocation) ----------------
// Weight hi plane: fp16 fragments. Per (m,n): 2048 frags; frag = w8g*64 + ks*4 + ctl.
// hi frag = 32 lanes * 4 halves = 256 B. Stage block (4 frags) = 1024 B contiguous.
__device__ __align__(1024) __half  g_Bhi[3u * NS * 2048u * 128u];   // 56.6 MB
// Weight lo plane: e5m2 bytes of (Wlo * 2^12). Stage block = 512 B contiguous.
__device__ __align__(1024) uint8_t g_Blo[3u * NS * 2048u * 128u];   // 28.3 MB
// h buffers (hi only now): [ks][rt][lane][8 halves] = 8192 halves (16 KB) per (parity, n).
__device__ __align__(1024) __half g_H1[2][NS][8192];
__device__ __align__(1024) __half g_H2[2][NS][8192];
__device__ float  g_c1[NS * HH * BB];
__device__ float  g_c2[NS * HH * BB];
__device__ float  g_Wih1p[NS * GWW];                   // permuted gate order (u*4+gt)
__device__ float  g_bg1p[NS * GWW];
__device__ float  g_bg2p[NS * GWW];
__device__ float  g_featT[FEAT * BB];                  // featT[k][b]
__device__ float  g_act[BB * HH];                      // fc1 output (post-ReLU)

// grid barrier: per-block monotone flags (padded) + release word (replay-safe).
__device__ volatile unsigned g_flags[NB * 32];
__device__ volatile unsigned g_rel;

// ---------------- PTX helpers ----------------
__device__ __forceinline__ uint32_t smem_u32(const void* p) {
    uint32_t a;
    asm("{ .reg .u64 t; cvta.to.shared.u64 t, %1; cvt.u32.u64 %0, t; }" : "=r"(a) : "l"(p));
    return a;
}
__device__ __forceinline__ void cp_async16(uint32_t dst, const void* src) {
    asm volatile("cp.async.cg.shared.global [%0], [%1], 16;" :: "r"(dst), "l"(src) : "memory");
}
__device__ __forceinline__ void cp_commit() {
    asm volatile("cp.async.commit_group;" ::: "memory");
}
__device__ __forceinline__ void cp_wait2() {
    asm volatile("cp.async.wait_group 2;" ::: "memory");
}
// L2-only (coherent, no L1 allocation) 16-byte global load for A (h) fragments.
__device__ __forceinline__ void ldg_cg128(uint4& v, const void* p) {
    asm volatile("ld.global.cg.v4.b32 {%0,%1,%2,%3}, [%4];"
                 : "=r"(v.x), "=r"(v.y), "=r"(v.z), "=r"(v.w) : "l"(p));
}
__device__ __forceinline__ void lds64v(uint2& v, uint32_t addr) {
    asm volatile("ld.shared.v2.b32 {%0,%1}, [%2];" : "=r"(v.x), "=r"(v.y) : "r"(addr));
}
__device__ __forceinline__ uint32_t lds32(uint32_t addr) {
    uint32_t v;
    asm volatile("ld.shared.b32 %0, [%1];" : "=r"(v) : "r"(addr));
    return v;
}
__device__ __forceinline__ uint32_t mulf16x2(uint32_t a, uint32_t b) {
    uint32_t d;
    asm("mul.f16x2 %0, %1, %2;" : "=r"(d) : "r"(a), "r"(b));
    return d;
}
__device__ __forceinline__ void mma16816(float c[4],
                                         uint32_t a0, uint32_t a1, uint32_t a2, uint32_t a3,
                                         uint32_t b0, uint32_t b1) {
    asm volatile(
        "mma.sync.aligned.m16n8k16.row.col.f32.f16.f16.f32 "
        "{%0,%1,%2,%3}, {%4,%5,%6,%7}, {%8,%9}, {%0,%1,%2,%3};"
        : "+f"(c[0]), "+f"(c[1]), "+f"(c[2]), "+f"(c[3])
        : "r"(a0), "r"(a1), "r"(a2), "r"(a3), "r"(b0), "r"(b1));
}
__device__ __forceinline__ float sigf(float v) { return 1.0f / (1.0f + expf(-v)); }

// Flag-array grid barrier (all NB blocks co-resident, single wave).
__device__ __forceinline__ void grid_barrier(unsigned target) {
    __syncthreads();
    if (blockIdx.x == 0) {
        if (threadIdx.x == 0) {
            __threadfence();
            g_flags[0] = target;
        }
        for (int j = threadIdx.x; j < NB; j += 256) {
            while (g_flags[j * 32] < target) { }
        }
        __syncthreads();
        if (threadIdx.x == 0) {
            __threadfence();
            g_rel = target;
        }
    } else {
        if (threadIdx.x == 0) {
            __threadfence();
            g_flags[blockIdx.x * 32] = target;
            while (g_rel < target) { }
        }
    }
    __syncthreads();
    __threadfence();
}

// ---------------- setup kernels ----------------
// Convert big weights fp32 -> hi plane (fp16) + lo plane (e5m2 of Wlo*2^12).
__global__ void conv_big(const float* __restrict__ Whh1,
                         const float* __restrict__ Wih2,
                         const float* __restrict__ Whh2) {
    int idx = blockIdx.x * 256 + threadIdx.x;        // 3*36*2048*32 = 7,077,888
    if (idx >= 3 * NS * 2048 * 32) return;
    int lane = idx & 31;
    int r    = idx >> 5;
    int frag = r & 2047;          // w8g*64 + ks*4 + ctl
    int r2   = r >> 11;
    int n    = r2 % NS;
    int m    = r2 / NS;
    int ctl  = frag & 3;
    int ks   = (frag >> 2) & 15;
    int w8g  = frag >> 6;         // [0,32): global warp-column index
    int col  = w8g * 32 + ctl * 8 + (lane >> 2);   // permuted gate-col [0,1024)
    int i4   = lane & 3;
    int u    = col >> 2;
    int gt   = col & 3;
    int g_orig = gt * 256 + u;    // original torch gate index
    const float* W = (m == 0) ? Whh1 : ((m == 1) ? Wih2 : Whh2);
    const float* src = W + ((size_t)n * GWW + g_orig) * HH + ks * 16;
    size_t fragGlobal = (size_t)(m * NS + n) * 2048 + frag;
    __half*  hiDst = g_Bhi + fragGlobal * 128 + lane * 4;
    uint8_t* loDst = g_Blo + fragGlobal * 128 + lane * 4;
    int kk0 = 2 * i4;
    int kks[4] = {kk0, kk0 + 1, kk0 + 8, kk0 + 9};
#pragma unroll
    for (int j = 0; j < 4; j++) {
        float v = src[kks[j]];
        __half hi = __float2half_rn(v);
        float rlo = (v - __half2float(hi)) * 4096.0f;   // 2^12 pre-scale
        __nv_fp8_e5m2 f8(rlo);                          // RN to e5m2
        hiDst[j] = hi;
        loDst[j] = *reinterpret_cast<uint8_t*>(&f8);
    }
}

// Permute Wih1 and fused biases into u*4+gt order.
__global__ void conv_small(const float* __restrict__ Wih1,
                           const float* __restrict__ bih1, const float* __restrict__ bhh1,
                           const float* __restrict__ bih2, const float* __restrict__ bhh2) {
    int idx = blockIdx.x * 256 + threadIdx.x;        // 36*1024
    if (idx >= NS * GWW) return;
    int n = idx >> 10;
    int col = idx & 1023;
    int u = col >> 2, gt = col & 3;
    int go = gt * 256 + u;
    int s = n * GWW + go;
    g_Wih1p[idx] = Wih1[s];
    g_bg1p[idx]  = bih1[s] + bhh1[s];
    g_bg2p[idx]  = bih2[s] + bhh2[s];
}

__global__ void init_kernel() {
    int idx = blockIdx.x * 256 + threadIdx.x;
    if (idx < 2 * NS * 8192 / 2) {                   // both parities (u32 count)
        ((uint32_t*)g_H1)[idx] = 0u;
        ((uint32_t*)g_H2)[idx] = 0u;
    }
    if (idx < NS * HH * BB) {
        g_c1[idx] = 0.f;
        g_c2[idx] = 0.f;
    }
}

// ---------------- persistent step kernel ----------------
// blocks [0,144) = layer1, [144,288) = layer2 (one step behind); 129 iterations
// separated by the flag-array grid barrier.
// 8 warps/block; warp w8 owns 32 output cols (4 ct-tiles) + a private 4-deep
// cp.async ring for weights. A (h) is read with ld.global.cg (L2-only: coherent
// across SMs and no L1 pollution). 2-term hi/lo MMA: Hhi*Whi + Hhi*Wlo.
__global__ void __launch_bounds__(256, 2) steps_kernel(
    const float* __restrict__ x,
    const float* __restrict__ spec,
    const float* __restrict__ Wspec,
    const float* __restrict__ bspec) {
    extern __shared__ __align__(128) unsigned char smem[];
    uint32_t smem_base = smem_u32(smem);

    int bid = blockIdx.x;
    bool isL2 = (bid >= 144);
    int lb = isL2 ? bid - 144 : bid;
    int n = lb >> 2, bl = lb & 3;
    int tid = threadIdx.x, w8 = tid >> 5, lane = tid & 31;
    int w8g = bl * 8 + w8;

    unsigned bar_base = g_flags[bid * 32];   // monotone across replays

    uint32_t ringBase = smem_base + (uint32_t)w8 * (DEPTH * SLOT_BYTES);
    uint32_t laneOff  = (uint32_t)lane * 16;

    const int S = isL2 ? 32 : 16;            // stages
    const int m0 = isL2 ? 1 : 0;
    const char* BhiBase = (const char*)g_Bhi;
    const char* BloBase = (const char*)g_Blo;
    const size_t warpHi0 = ((size_t)((m0 * NS) + n) * 2048 + (size_t)w8g * 64) * 256;
    const size_t warpHi1 = ((size_t)(((m0 + 1) * NS) + n) * 2048 + (size_t)w8g * 64) * 256;
    const size_t warpLo0 = ((size_t)((m0 * NS) + n) * 2048 + (size_t)w8g * 64) * 128;
    const size_t warpLo1 = ((size_t)(((m0 + 1) * NS) + n) * 2048 + (size_t)w8g * 64) * 128;

    float* cbuf = isL2 ? g_c2 : g_c1;
    const float* bias = isL2 ? g_bg2p : g_bg1p;

    for (int t = 0; t <= TST; t++) {
        int st = isL2 ? t - 1 : t;
        if (st >= 0 && st < TST) {
            int rp = st & 1, wp = rp ^ 1;
            const uint4* Ahi0 = (const uint4*)(isL2 ? g_H1[wp][n] : g_H1[rp][n]);
            const uint4* Ahi1 = (const uint4*)g_H2[rp][n];   // stages >=16 (isL2 only)

            // prologue: issue stages 0..2
#pragma unroll
            for (int s = 0; s < 3; s++) {
                if (s < S) {
                    size_t hoff = ((s < 16) ? warpHi0 : warpHi1) + (size_t)(s & 15) * 1024;
                    size_t loff = ((s < 16) ? warpLo0 : warpLo1) + (size_t)(s & 15) * 512;
                    uint32_t dst = ringBase + (uint32_t)(s & (DEPTH - 1)) * SLOT_BYTES;
                    cp_async16(dst + laneOff,        BhiBase + hoff + laneOff);
                    cp_async16(dst + 512 + laneOff,  BhiBase + hoff + 512 + laneOff);
                    cp_async16(dst + 1024 + laneOff, BloBase + loff + laneOff);
                }
                cp_commit();
            }

            float acc[2][4][4];
#pragma unroll
            for (int a = 0; a < 2; a++)
#pragma unroll
                for (int b = 0; b < 4; b++)
#pragma unroll
                    for (int c = 0; c < 4; c++) acc[a][b][c] = 0.f;

            for (int s = 0; s < S; s++) {
                int slot = s & (DEPTH - 1);
                cp_wait2();                      // own groups <= 2 pending
                __syncwarp();                    // all lanes' stage-s copies visible
                int ks = s & 15;
                const uint4* A = (s < 16) ? Ahi0 : Ahi1;

                uint4 ahi[2];
#pragma unroll
                for (int rt = 0; rt < 2; rt++)
                    ldg_cg128(ahi[rt], A + (ks * 2 + rt) * 32 + lane);   // 512 B contiguous

                uint32_t slotAddr = ringBase + slot * SLOT_BYTES;
                uint2 bhi[4];
                uint32_t lo32[4];
#pragma unroll
                for (int ctl = 0; ctl < 4; ctl++) {
                    lds64v(bhi[ctl], slotAddr + ctl * 256 + lane * 8);
                    lo32[ctl] = lds32(slotAddr + 1024 + ctl * 128 + lane * 4);
                }

                // refill slot (s+3)&3 for stage s+3
                int s2 = s + 3;
                if (s2 < S) {
                    size_t hoff = ((s2 < 16) ? warpHi0 : warpHi1) + (size_t)(s2 & 15) * 1024;
                    size_t loff = ((s2 < 16) ? warpLo0 : warpLo1) + (size_t)(s2 & 15) * 512;
                    uint32_t dst = ringBase + (uint32_t)(s2 & (DEPTH - 1)) * SLOT_BYTES;
                    cp_async16(dst + laneOff,        BhiBase + hoff + laneOff);
                    cp_async16(dst + 512 + laneOff,  BhiBase + hoff + 512 + laneOff);
                    cp_async16(dst + 1024 + laneOff, BloBase + loff + laneOff);
                }
                cp_commit();

#pragma unroll
                for (int ctl = 0; ctl < 4; ctl++) {
                    // expand e5m2 -> fp16 (exact: byte<<8), rescale by 2^-12 (exact)
                    uint32_t l0 = __byte_perm(lo32[ctl], 0u, 0x1404);
                    uint32_t l1 = __byte_perm(lo32[ctl], 0u, 0x3424);
                    l0 = mulf16x2(l0, 0x0C000C00u);
                    l1 = mulf16x2(l1, 0x0C000C00u);
#pragma unroll
                    for (int rt = 0; rt < 2; rt++) {
                        mma16816(acc[rt][ctl], ahi[rt].x, ahi[rt].y, ahi[rt].z, ahi[rt].w, bhi[ctl].x, bhi[ctl].y);  // Hhi*Whi
                        mma16816(acc[rt][ctl], ahi[rt].x, ahi[rt].y, ahi[rt].z, ahi[rt].w, l0, l1);                  // Hhi*Wlo
                    }
                }
            }

            // sg overlays the ring (all async copies drained)
            asm volatile("cp.async.wait_group 0;" ::: "memory");
            __syncthreads();
            float* sg = (float*)smem;            // 32 KB <= 48 KB ring

            int g8 = lane >> 2;
            int i2 = (lane & 3) * 2;
#pragma unroll
            for (int rt = 0; rt < 2; rt++)
#pragma unroll
                for (int ctl = 0; ctl < 4; ctl++) {
                    int col = w8 * 32 + ctl * 8 + i2;
                    int r0 = rt * 16 + g8;
                    sg[r0 * 256 + col]           = acc[rt][ctl][0];
                    sg[r0 * 256 + col + 1]       = acc[rt][ctl][1];
                    sg[(r0 + 8) * 256 + col]     = acc[rt][ctl][2];
                    sg[(r0 + 8) * 256 + col + 1] = acc[rt][ctl][3];
                }
            __syncthreads();

            __half* Hout = isL2 ? g_H2[wp][n] : g_H1[wp][n];

            for (int e = tid; e < BB * 64; e += 256) {
                int b  = e & 31;
                int ul = e >> 5;                 // local unit [0,64)
                int u  = bl * 64 + ul;           // unit [0,256)
                int cb = ul * 4;
                int colg = bl * 256 + cb;        // permuted col within stream
                float ip = sg[b * 256 + cb + 0] + bias[n * GWW + colg + 0];
                float fp = sg[b * 256 + cb + 1] + bias[n * GWW + colg + 1];
                float gp = sg[b * 256 + cb + 2] + bias[n * GWW + colg + 2];
                float op = sg[b * 256 + cb + 3] + bias[n * GWW + colg + 3];
                if (!isL2) {
                    float xv = x[(b * TST + st) * NS + n];
                    ip += xv * g_Wih1p[n * GWW + colg + 0];
                    fp += xv * g_Wih1p[n * GWW + colg + 1];
                    gp += xv * g_Wih1p[n * GWW + colg + 2];
                    op += xv * g_Wih1p[n * GWW + colg + 3];
                }
                float iv = sigf(ip), fv = sigf(fp), gv = tanhf(gp), ov = sigf(op);
                int ci = (n * HH + u) * BB + b;
                float cv = fv * cbuf[ci] + iv * gv;
                cbuf[ci] = cv;
                float hv = ov * tanhf(cv);

                // write h (hi only) into A-fragment layout
                int ks = u >> 4, kk = u & 15;
                int rt = b >> 4, rl = b & 15;
                int gg = rl & 7, hirow = rl >> 3;
                int ii = (kk & 7) >> 1, p = kk & 1, hik = kk >> 3;
                int lane2 = gg * 4 + ii;
                int j = hik * 4 + hirow * 2 + p;
                Hout[((ks * 2 + rt) * 32 + lane2) * 8 + j] = __float2half_rn(hv);

                if (isL2) g_featT[(n * HH + u) * BB + b] = hv;
            }
        } else if (!isL2 && bid == 0 && t == TST) {
            // idle final iteration: compute spec-dense rows of featT
            int j = tid;                         // [0,256)
            for (int b = 0; b < BB; b++) {
                float s = bspec[j];
#pragma unroll
                for (int i = 0; i < 6; i++) s += spec[b * 6 + i] * Wspec[i * HH + j];
                g_featT[(NS * HH + j) * BB + b] = s;
            }
        }

        grid_barrier(bar_base + (unsigned)t + 1u);   // publishes h(t)
    }
}

// ---------------- classifier ----------------
__global__ void fc1_kernel(const float* __restrict__ Wp1, const float* __restrict__ bp1) {
    int tid = threadIdx.x;
    int b = tid & 31;
    int tj = tid >> 5;                      // [0,8)
    int j = blockIdx.x * 8 + tj;            // [0,256)
    const float* ft = g_featT + b;
    const float* wc = Wp1 + j;
    float a0 = 0.f, a1 = 0.f, a2 = 0.f, a3 = 0.f;
#pragma unroll 4
    for (int k = 0; k < FEAT; k += 4) {
        a0 += ft[(k + 0) * BB] * wc[(size_t)(k + 0) * HH];
        a1 += ft[(k + 1) * BB] * wc[(size_t)(k + 1) * HH];
        a2 += ft[(k + 2) * BB] * wc[(size_t)(k + 2) * HH];
        a3 += ft[(k + 3) * BB] * wc[(size_t)(k + 3) * HH];
    }
    float acc = bp1[j] + ((a0 + a1) + (a2 + a3));
    g_act[b * HH + j] = fmaxf(acc, 0.f);
}

__global__ void fc2_kernel(const float* __restrict__ Wp2, const float* __restrict__ bp2,
                           float* __restrict__ out) {
    int tid = threadIdx.x;
    if (tid >= BB * 30) return;
    int b = tid / 30, o = tid % 30;
    float acc = bp2[o];
#pragma unroll 8
    for (int k = 0; k < HH; k++) acc += g_act[b * HH + k] * Wp2[k * 30 + o];
    out[b * 30 + o] = acc;
}

// ---------------- launch ----------------
extern "C" void kernel_launch(void* const* d_in, const int* in_sizes, int n_in,
                              void* d_out, int out_size) {
    const float* x     = (const float*)d_in[0];
    const float* spec  = (const float*)d_in[1];
    const float* Wih1  = (const float*)d_in[2];
    const float* Whh1  = (const float*)d_in[3];
    const float* bih1  = (const float*)d_in[4];
    const float* bhh1  = (const float*)d_in[5];
    const float* Wih2  = (const float*)d_in[6];
    const float* Whh2  = (const float*)d_in[7];
    const float* bih2  = (const float*)d_in[8];
    const float* bhh2  = (const float*)d_in[9];
    const float* Wspec = (const float*)d_in[10];
    const float* bspec = (const float*)d_in[11];
    const float* Wp1   = (const float*)d_in[12];
    const float* bp1   = (const float*)d_in[13];
    const float* Wp2   = (const float*)d_in[14];
    const float* bp2   = (const float*)d_in[15];
    float* out = (float*)d_out;

    cudaFuncSetAttribute(steps_kernel, cudaFuncAttributeMaxDynamicSharedMemorySize, SMEM_BYTES);

    conv_big<<<27648, 256>>>(Whh1, Wih2, Whh2);
    conv_small<<<144, 256>>>(Wih1, bih1, bhh1, bih2, bhh2);
    init_kernel<<<2304, 256>>>();

    steps_kernel<<<NB, 256, SMEM_BYTES>>>(x, spec, Wspec, bspec);

    fc1_kernel<<<32, 256>>>(Wp1, bp1);
    fc2_kernel<<<1, 960>>>(Wp2, bp2, out);
}